// round 15
// baseline (speedup 1.0000x reference)
#include <cuda_runtime.h>
#include <math.h>

// Problem constants (fixed by the reference)
#define S_LEN   1024
#define I_DIM   1024
#define H_DIM   2048
#define L_NUM   4

#define SCAN_CTAS     128
#define ROWS_PER_CTA  16              // H_DIM / SCAN_CTAS
#define SCAN_THREADS  256             // 8 warps: 2 row-groups x 4 K-slices
#define SCAN_SMEM_BYTES (ROWS_PER_CTA * H_DIM * (int)sizeof(float))  // 131072 (weights)
#define CNT_STRIDE 64                 // 256B stride between per-step counters
#define ARRIVALS_PER_STEP SCAN_CTAS   // funneled: ONE red per CTA per step

// Scratch (device globals — no allocation allowed)
__device__ float g_U [S_LEN * H_DIM];            // u_l(t) for current layer (8 MB)
__device__ float g_HA[S_LEN * H_DIM];            // hidden states of current layer (8 MB)
__device__ int   g_cnt[S_LEN * CNT_STRIDE];      // strided per-timestep arrival counters

// ---------------------------------------------------------------------------
// Sync rules banked this session:
//  1. Poll ONLY with morally-strong loads (R4/R7/R8 failed on weak ld.cg).
//     ld.relaxed.gpu IS morally strong (R5/R9 passed with it).
//  2. ONE warp polls globally per CTA; relay intra-CTA via SMEM
//     (R6/R14 12ms vs R5/R9 all-warp polling 15.1ms).
//  3. Release fence must execute in the STORING thread (R4 failure).
//  4. Per-warp full-H h loads = hidden L2 cost -> K-split (R14 win).
//  5. THIS ROUND: single-poller probes with RELAXED (cheap) instead of
//     per-probe ACQUIRE (heavy), one fence on success — the one untested
//     cell of the (probe strength x polling structure) matrix.
// ---------------------------------------------------------------------------
__device__ __forceinline__ int ld_relaxed_gpu(const int* p) {
    int v;
    asm volatile("ld.relaxed.gpu.global.s32 %0, [%1];" : "=r"(v) : "l"(p) : "memory");
    return v;
}
__device__ __forceinline__ void fence_gpu() {
    asm volatile("fence.acq_rel.gpu;" ::: "memory");
}
__device__ __forceinline__ void red_release_gpu(int* p) {
    asm volatile("red.release.gpu.global.add.s32 [%0], 1;" :: "l"(p) : "memory");
}
__device__ __forceinline__ void st_release_shared(int* p, int v) {
    unsigned a = (unsigned)__cvta_generic_to_shared(p);
    asm volatile("st.release.cta.shared.s32 [%0], %1;" :: "r"(a), "r"(v) : "memory");
}
__device__ __forceinline__ int ld_acquire_shared(const int* p) {
    unsigned a = (unsigned)__cvta_generic_to_shared(p);
    int v;
    asm volatile("ld.acquire.cta.shared.s32 %0, [%1];" : "=r"(v) : "r"(a) : "memory");
    return v;
}

// ---------------------------------------------------------------------------
// GEMM: C[M,N] = A[M,K] @ B[N,K]^T + bias1[n] + bias2[n]
// 128x128 tile, BK=8, 256 threads, 8x8 per-thread microtile. (Proven; unchanged.)
// ---------------------------------------------------------------------------
__global__ void gemm_bias_kernel(const float* __restrict__ A,
                                 const float* __restrict__ B,
                                 float* __restrict__ C,
                                 const float* __restrict__ bias1,
                                 const float* __restrict__ bias2,
                                 int M, int N, int K)
{
    __shared__ float As[8][128];
    __shared__ float Bs[8][128];

    const int tid = threadIdx.x;
    const int bm  = blockIdx.y * 128;
    const int bn  = blockIdx.x * 128;

    const int loadRow = tid >> 1;        // 0..127
    const int loadCol = (tid & 1) * 4;   // 0 or 4

    const int tx = tid & 15;             // n sub-tile
    const int ty = tid >> 4;             // m sub-tile

    float acc[8][8];
#pragma unroll
    for (int i = 0; i < 8; i++)
#pragma unroll
        for (int j = 0; j < 8; j++) acc[i][j] = 0.f;

    const float* Ag = A + (size_t)(bm + loadRow) * K + loadCol;
    const float* Bg = B + (size_t)(bn + loadRow) * K + loadCol;

    for (int k0 = 0; k0 < K; k0 += 8) {
        float4 av = *(const float4*)(Ag + k0);
        float4 bv = *(const float4*)(Bg + k0);
        As[loadCol + 0][loadRow] = av.x;
        As[loadCol + 1][loadRow] = av.y;
        As[loadCol + 2][loadRow] = av.z;
        As[loadCol + 3][loadRow] = av.w;
        Bs[loadCol + 0][loadRow] = bv.x;
        Bs[loadCol + 1][loadRow] = bv.y;
        Bs[loadCol + 2][loadRow] = bv.z;
        Bs[loadCol + 3][loadRow] = bv.w;
        __syncthreads();

#pragma unroll
        for (int k = 0; k < 8; k++) {
            float a[8], b[8];
#pragma unroll
            for (int i = 0; i < 8; i++) a[i] = As[k][ty * 8 + i];
#pragma unroll
            for (int j = 0; j < 8; j++) b[j] = Bs[k][tx * 8 + j];
#pragma unroll
            for (int i = 0; i < 8; i++)
#pragma unroll
                for (int j = 0; j < 8; j++)
                    acc[i][j] += a[i] * b[j];
        }
        __syncthreads();
    }

    // Epilogue with fused bias add, float4 stores
#pragma unroll
    for (int i = 0; i < 8; i++) {
        const int m = bm + ty * 8 + i;
        float* crow = C + (size_t)m * N + bn + tx * 8;
#pragma unroll
        for (int j = 0; j < 8; j += 4) {
            const int n = bn + tx * 8 + j;
            float4 v;
            v.x = acc[i][j + 0] + bias1[n + 0] + bias2[n + 0];
            v.y = acc[i][j + 1] + bias1[n + 1] + bias2[n + 1];
            v.z = acc[i][j + 2] + bias1[n + 2] + bias2[n + 2];
            v.w = acc[i][j + 3] + bias1[n + 3] + bias2[n + 3];
            *(float4*)(crow + j) = v;
        }
    }
}

// ---------------------------------------------------------------------------
// Persistent scan, K-SPLIT (R14-proven) with relaxed single-poller (new):
// h(t) = tanh(U[t] + Wh @ h(t-1)).
// Wh sliced across 128 CTAs' SMEM (16 rows each). 8 warps per CTA as
// 2 row-groups x 4 K-slices; each warp loads only its 2KB h-chunk.
// Per step:
//   wait:   warp0 polls cnt[t-1] with CHEAP ld.relaxed.gpu probes, executes
//           ONE fence.acq_rel.gpu on success (R5/R9-proven morally-strong
//           pattern), relays via s_flag (R6-proven release/acquire).
//   load:   4 ldcg float4 per lane, issued upfront.
//   compute: 4 iters x (8 rows LDS.128 + 32 FFMA).
//   reduce: shfl -> s_part -> __syncthreads -> warp0 funnel: sum 4 slices +
//           tanh + st.cg + fence in storer + ONE red.release per CTA.
// ---------------------------------------------------------------------------
__global__ void __launch_bounds__(SCAN_THREADS, 1)
scan_kernel(const float* __restrict__ Wh,    // layer's H x H row-major slice base
            const float* __restrict__ U,     // S x H (biases already folded in)
            float* __restrict__ Hout,        // S x H; reads t-1, writes t
            int* cnt,                        // strided arrival counters
            int wait_target)                 // 128*(layer+1)
{
    extern __shared__ float smem[];
    float* sW = smem;                         // ROWS_PER_CTA * H_DIM floats
    __shared__ float s_part[4 * ROWS_PER_CTA];// partials: [kslice][row]
    __shared__ int   s_flag;                  // intra-CTA step relay (monotonic)

    const int tid  = threadIdx.x;
    const int lane = tid & 31;
    const int warp = tid >> 5;                // 0..7
    const int rgrp = warp >> 2;               // 0..1 (row group)
    const int ksl  = warp & 3;                // 0..3 (K slice)
    const int row0 = blockIdx.x * ROWS_PER_CTA;
    const int r0   = rgrp * 8;                // first local row of this warp
    const int kq   = ksl * 128;               // K-chunk base in float4 units (512 floats)

    // Stage this CTA's 16 weight rows into SMEM (contiguous rows, coalesced)
    {
        const float4* Wg  = (const float4*)(Wh + (size_t)row0 * H_DIM);
        float4* sW4 = (float4*)sW;
        const int nvec = ROWS_PER_CTA * H_DIM / 4;
        for (int i = tid; i < nvec; i += SCAN_THREADS) sW4[i] = Wg[i];
    }
    if (tid == 0) s_flag = 0;
    __syncthreads();

    // Per-warp weight row pointers (float4), offset to this warp's K-chunk
    const float4* wr[8];
#pragma unroll
    for (int j = 0; j < 8; j++)
        wr[j] = (const float4*)(sW + (size_t)(r0 + j) * H_DIM) + kq;

    for (int t = 0; t < S_LEN; t++) {
        // warp0 preloads U for all 16 rows (stable data, before the wait)
        float uval = 0.f;
        if (warp == 0 && lane < ROWS_PER_CTA)
            uval = __ldg(U + (size_t)t * H_DIM + row0 + lane);

        float a0 = 0.f, a1 = 0.f, a2 = 0.f, a3 = 0.f;
        float a4 = 0.f, a5 = 0.f, a6 = 0.f, a7 = 0.f;

        if (t > 0) {
            if (warp == 0) {
                // Cheap relaxed probes; ONE acquire-side fence on success.
                while (ld_relaxed_gpu(cnt + (size_t)(t - 1) * CNT_STRIDE) < wait_target) { }
                fence_gpu();
                if (lane == 0) st_release_shared(&s_flag, t);
            } else {
                while (ld_acquire_shared(&s_flag) < t) { }
            }

            // This warp's 2KB h-chunk: 4 float4 per lane, all in flight at once
            const float4* hp4 = (const float4*)(Hout + (size_t)(t - 1) * H_DIM) + kq;
            float4 hb0 = __ldcg(hp4 + lane);
            float4 hb1 = __ldcg(hp4 + lane + 32);
            float4 hb2 = __ldcg(hp4 + lane + 64);
            float4 hb3 = __ldcg(hp4 + lane + 96);

#pragma unroll
            for (int i = 0; i < 4; i++) {
                const float4 hv = (i == 0) ? hb0 : (i == 1) ? hb1
                                : (i == 2) ? hb2 : hb3;
                const int idx = lane + 32 * i;
                float4 x;
                x = wr[0][idx]; a0 += x.x*hv.x + x.y*hv.y + x.z*hv.z + x.w*hv.w;
                x = wr[1][idx]; a1 += x.x*hv.x + x.y*hv.y + x.z*hv.z + x.w*hv.w;
                x = wr[2][idx]; a2 += x.x*hv.x + x.y*hv.y + x.z*hv.z + x.w*hv.w;
                x = wr[3][idx]; a3 += x.x*hv.x + x.y*hv.y + x.z*hv.z + x.w*hv.w;
                x = wr[4][idx]; a4 += x.x*hv.x + x.y*hv.y + x.z*hv.z + x.w*hv.w;
                x = wr[5][idx]; a5 += x.x*hv.x + x.y*hv.y + x.z*hv.z + x.w*hv.w;
                x = wr[6][idx]; a6 += x.x*hv.x + x.y*hv.y + x.z*hv.z + x.w*hv.w;
                x = wr[7][idx]; a7 += x.x*hv.x + x.y*hv.y + x.z*hv.z + x.w*hv.w;
            }
#pragma unroll
            for (int off = 16; off > 0; off >>= 1) {
                a0 += __shfl_xor_sync(0xffffffffu, a0, off);
                a1 += __shfl_xor_sync(0xffffffffu, a1, off);
                a2 += __shfl_xor_sync(0xffffffffu, a2, off);
                a3 += __shfl_xor_sync(0xffffffffu, a3, off);
                a4 += __shfl_xor_sync(0xffffffffu, a4, off);
                a5 += __shfl_xor_sync(0xffffffffu, a5, off);
                a6 += __shfl_xor_sync(0xffffffffu, a6, off);
                a7 += __shfl_xor_sync(0xffffffffu, a7, off);
            }
        }

        // lanes 0-7 park this warp's 8 row-partials in SMEM
        if (lane < 8) {
            const float v = (lane == 0) ? a0 : (lane == 1) ? a1
                          : (lane == 2) ? a2 : (lane == 3) ? a3
                          : (lane == 4) ? a4 : (lane == 5) ? a5
                          : (lane == 6) ? a6 : a7;
            s_part[ksl * ROWS_PER_CTA + r0 + lane] = v;
        }
        __syncthreads();   // all partials visible to warp0

        // warp0 funnel: sum 4 K-slices, tanh, store, fence in storer, one red
        if (warp == 0) {
            if (lane < ROWS_PER_CTA) {
                const float s = s_part[lane]
                              + s_part[ROWS_PER_CTA + lane]
                              + s_part[2 * ROWS_PER_CTA + lane]
                              + s_part[3 * ROWS_PER_CTA + lane];
                __stcg(Hout + (size_t)t * H_DIM + row0 + lane, tanhf(uval + s));
                fence_gpu();                    // R2-proven: fence by the storer
            }
            __syncwarp();
            if (lane == 0) red_release_gpu(cnt + (size_t)t * CNT_STRIDE);
        }
    }
}

// ---------------------------------------------------------------------------
extern "C" void kernel_launch(void* const* d_in, const int* in_sizes, int n_in,
                              void* d_out, int out_size)
{
    const float* input = (const float*)d_in[0];   // (1, S, I)
    const float* Wi0   = (const float*)d_in[1];   // (H, I)
    const float* bi0   = (const float*)d_in[2];   // (H)
    const float* WiR   = (const float*)d_in[3];   // (L-1, H, H)
    const float* biR   = (const float*)d_in[4];   // (L-1, H)
    const float* Wh    = (const float*)d_in[5];   // (L, H, H)
    const float* bh    = (const float*)d_in[6];   // (L, H)
    float* out = (float*)d_out;                   // (S, 1, H) contiguous

    float *U, *HA; int* cnt;
    cudaGetSymbolAddress((void**)&U,  g_U);
    cudaGetSymbolAddress((void**)&HA, g_HA);
    cudaGetSymbolAddress((void**)&cnt, g_cnt);

    cudaFuncSetAttribute(scan_kernel,
                         cudaFuncAttributeMaxDynamicSharedMemorySize,
                         SCAN_SMEM_BYTES);

    // Counters must be zero at the start of every replay (graph-captured node)
    cudaMemsetAsync(cnt, 0, S_LEN * CNT_STRIDE * sizeof(int));

    dim3 gemm_grid(H_DIM / 128, S_LEN / 128);   // (16, 8)

    // Layer 0: U = X @ Wi0^T + bi0 + bh[0]; then scan with Wh[0]
    gemm_bias_kernel<<<gemm_grid, 256>>>(input, Wi0, U, bi0, bh, S_LEN, H_DIM, I_DIM);
    scan_kernel<<<SCAN_CTAS, SCAN_THREADS, SCAN_SMEM_BYTES>>>(Wh, U, HA, cnt,
                                                              ARRIVALS_PER_STEP);

    // Layers 1..3
    for (int l = 1; l < L_NUM; l++) {
        const float* Wi_l = WiR + (size_t)(l - 1) * H_DIM * H_DIM;
        const float* bi_l = biR + (size_t)(l - 1) * H_DIM;
        const float* Wh_l = Wh  + (size_t)l * H_DIM * H_DIM;
        const float* bh_l = bh  + (size_t)l * H_DIM;
        float* dst = (l == L_NUM - 1) ? out : HA;

        gemm_bias_kernel<<<gemm_grid, 256>>>(HA, Wi_l, U, bi_l, bh_l,
                                             S_LEN, H_DIM, H_DIM);
        scan_kernel<<<SCAN_CTAS, SCAN_THREADS, SCAN_SMEM_BYTES>>>(Wh_l, U, dst, cnt,
                                                                  ARRIVALS_PER_STEP * (l + 1));
    }
}

// round 17
// speedup vs baseline: 1.1270x; 1.1270x over previous
#include <cuda_runtime.h>
#include <math.h>

// Problem constants (fixed by the reference)
#define S_LEN   1024
#define I_DIM   1024
#define H_DIM   2048
#define L_NUM   4

#define SCAN_CTAS     128
#define ROWS_PER_CTA  16              // H_DIM / SCAN_CTAS
#define SCAN_THREADS  256             // 8 warps: 2 row-groups x 4 K-slices
#define SCAN_SMEM_BYTES (ROWS_PER_CTA * H_DIM * (int)sizeof(float))  // 131072 (weights)
#define CNT_STRIDE 64                 // 256B stride between per-step counters
#define ARRIVALS_PER_STEP (SCAN_CTAS * 2)   // TWO reds per CTA (split commit) = 256

// Scratch (device globals — no allocation allowed)
__device__ float g_U [S_LEN * H_DIM];            // u_l(t) for current layer (8 MB)
__device__ float g_HA[S_LEN * H_DIM];            // hidden states of current layer (8 MB)
__device__ int   g_cnt[S_LEN * CNT_STRIDE];      // strided per-timestep arrival counters

// ---------------------------------------------------------------------------
// Sync rules banked this session:
//  1. Poll ONLY with morally-strong loads (R4/R7/R8 failed on weak ld.cg).
//  2. ONE warp polls globally per CTA; relay intra-CTA via SMEM
//     (R6/R14 ~12ms vs R5/R9 all-warp polling 15.1ms).
//  3. Release fence must execute in the STORING thread (R4 failure).
//  4. K-split warps to cut h L2 traffic (R14 win).
//  5. Probe with ACQUIRE, not relaxed: R15 (relaxed single-poller) regressed
//     13.3ms vs R14 11.9ms — relaxed spins faster and congests the counter
//     slice; acquire's heavier probe is self-pacing. Protocol axis CLOSED.
// ---------------------------------------------------------------------------
__device__ __forceinline__ int ld_acquire_gpu(const int* p) {
    int v;
    asm volatile("ld.acquire.gpu.global.s32 %0, [%1];" : "=r"(v) : "l"(p) : "memory");
    return v;
}
__device__ __forceinline__ void fence_gpu() {
    asm volatile("fence.acq_rel.gpu;" ::: "memory");
}
__device__ __forceinline__ void red_release_gpu(int* p) {
    asm volatile("red.release.gpu.global.add.s32 [%0], 1;" :: "l"(p) : "memory");
}
__device__ __forceinline__ void st_release_shared(int* p, int v) {
    unsigned a = (unsigned)__cvta_generic_to_shared(p);
    asm volatile("st.release.cta.shared.s32 [%0], %1;" :: "r"(a), "r"(v) : "memory");
}
__device__ __forceinline__ int ld_acquire_shared(const int* p) {
    unsigned a = (unsigned)__cvta_generic_to_shared(p);
    int v;
    asm volatile("ld.acquire.cta.shared.s32 %0, [%1];" : "=r"(v) : "r"(a) : "memory");
    return v;
}

// ---------------------------------------------------------------------------
// GEMM: C[M,N] = A[M,K] @ B[N,K]^T + bias1[n] + bias2[n]
// 128x128 tile, BK=8, 256 threads, 8x8 microtile. The next k-panel's LDG is
// issued BEFORE the compute phase, so its ~577-cyc DRAM latency retires
// under the ~1024-cyc FFMA block (was fully exposed).
// Barrier structure: sync -> STS -> sync -> (LDG next) -> compute.
// ---------------------------------------------------------------------------
__global__ void gemm_bias_kernel(const float* __restrict__ A,
                                 const float* __restrict__ B,
                                 float* __restrict__ C,
                                 const float* __restrict__ bias1,
                                 const float* __restrict__ bias2,
                                 int M, int N, int K)
{
    __shared__ float As[8][128];
    __shared__ float Bs[8][128];

    const int tid = threadIdx.x;
    const int bm  = blockIdx.y * 128;
    const int bn  = blockIdx.x * 128;

    const int loadRow = tid >> 1;        // 0..127
    const int loadCol = (tid & 1) * 4;   // 0 or 4

    const int tx = tid & 15;             // n sub-tile
    const int ty = tid >> 4;             // m sub-tile

    float acc[8][8];
#pragma unroll
    for (int i = 0; i < 8; i++)
#pragma unroll
        for (int j = 0; j < 8; j++) acc[i][j] = 0.f;

    const float* Ag = A + (size_t)(bm + loadRow) * K + loadCol;
    const float* Bg = B + (size_t)(bn + loadRow) * K + loadCol;

    // Prologue: panel 0 in flight
    float4 av = *(const float4*)(Ag);
    float4 bv = *(const float4*)(Bg);

    for (int k0 = 0; k0 < K; k0 += 8) {
        __syncthreads();                 // previous compute done reading smem
        As[loadCol + 0][loadRow] = av.x;
        As[loadCol + 1][loadRow] = av.y;
        As[loadCol + 2][loadRow] = av.z;
        As[loadCol + 3][loadRow] = av.w;
        Bs[loadCol + 0][loadRow] = bv.x;
        Bs[loadCol + 1][loadRow] = bv.y;
        Bs[loadCol + 2][loadRow] = bv.z;
        Bs[loadCol + 3][loadRow] = bv.w;
        __syncthreads();                 // panel visible to all

        // Issue NEXT panel's global loads; latency hides under compute below
        if (k0 + 8 < K) {
            av = *(const float4*)(Ag + k0 + 8);
            bv = *(const float4*)(Bg + k0 + 8);
        }

#pragma unroll
        for (int k = 0; k < 8; k++) {
            float a[8], b[8];
#pragma unroll
            for (int i = 0; i < 8; i++) a[i] = As[k][ty * 8 + i];
#pragma unroll
            for (int j = 0; j < 8; j++) b[j] = Bs[k][tx * 8 + j];
#pragma unroll
            for (int i = 0; i < 8; i++)
#pragma unroll
                for (int j = 0; j < 8; j++)
                    acc[i][j] += a[i] * b[j];
        }
    }

    // Epilogue with fused bias add, float4 stores
#pragma unroll
    for (int i = 0; i < 8; i++) {
        const int m = bm + ty * 8 + i;
        float* crow = C + (size_t)m * N + bn + tx * 8;
#pragma unroll
        for (int j = 0; j < 8; j += 4) {
            const int n = bn + tx * 8 + j;
            float4 v;
            v.x = acc[i][j + 0] + bias1[n + 0] + bias2[n + 0];
            v.y = acc[i][j + 1] + bias1[n + 1] + bias2[n + 1];
            v.z = acc[i][j + 2] + bias1[n + 2] + bias2[n + 2];
            v.w = acc[i][j + 3] + bias1[n + 3] + bias2[n + 3];
            *(float4*)(crow + j) = v;
        }
    }
}

// ---------------------------------------------------------------------------
// Persistent scan, K-SPLIT (R14-proven core, acquire single-poller):
// h(t) = tanh(U[t] + Wh @ h(t-1)).
// Wh sliced across 128 CTAs' SMEM (16 rows each). 8 warps per CTA as
// 2 row-groups x 4 K-slices; each warp loads only its 2KB h-chunk.
// SPLIT COMMIT: warps 0 and 4 each finalize their own row-group (8 rows):
// sum slices, tanh, st.cg, fence in storer, own red.release. 2 arrivals
// per CTA per step (target 256*(layer+1)); halves the serial funnel tail.
// s_part reuse race-free: warp0 publishes s_flag=t+1 only after cnt[t]
// reaches target, which includes warp4's red(t) issued AFTER warp4 read
// s_part(t).
// ---------------------------------------------------------------------------
__global__ void __launch_bounds__(SCAN_THREADS, 1)
scan_kernel(const float* __restrict__ Wh,    // layer's H x H row-major slice base
            const float* __restrict__ U,     // S x H (biases already folded in)
            float* __restrict__ Hout,        // S x H; reads t-1, writes t
            int* cnt,                        // strided arrival counters
            int wait_target)                 // 256*(layer+1)
{
    extern __shared__ float smem[];
    float* sW = smem;                         // ROWS_PER_CTA * H_DIM floats
    __shared__ float s_part[4 * ROWS_PER_CTA];// partials: [kslice][row]
    __shared__ int   s_flag;                  // intra-CTA step relay (monotonic)

    const int tid  = threadIdx.x;
    const int lane = tid & 31;
    const int warp = tid >> 5;                // 0..7
    const int rgrp = warp >> 2;               // 0..1 (row group)
    const int ksl  = warp & 3;                // 0..3 (K slice)
    const int row0 = blockIdx.x * ROWS_PER_CTA;
    const int r0   = rgrp * 8;                // first local row of this warp
    const int kq   = ksl * 128;               // K-chunk base in float4 units (512 floats)

    // Stage this CTA's 16 weight rows into SMEM (contiguous rows, coalesced)
    {
        const float4* Wg  = (const float4*)(Wh + (size_t)row0 * H_DIM);
        float4* sW4 = (float4*)sW;
        const int nvec = ROWS_PER_CTA * H_DIM / 4;
        for (int i = tid; i < nvec; i += SCAN_THREADS) sW4[i] = Wg[i];
    }
    if (tid == 0) s_flag = 0;
    __syncthreads();

    // Per-warp weight row pointers (float4), offset to this warp's K-chunk
    const float4* wr[8];
#pragma unroll
    for (int j = 0; j < 8; j++)
        wr[j] = (const float4*)(sW + (size_t)(r0 + j) * H_DIM) + kq;

    for (int t = 0; t < S_LEN; t++) {
        // Committing warps (0 and 4) preload U for their 8 rows before wait
        float uval = 0.f;
        if (ksl == 0 && lane < 8)
            uval = __ldg(U + (size_t)t * H_DIM + row0 + r0 + lane);

        float a0 = 0.f, a1 = 0.f, a2 = 0.f, a3 = 0.f;
        float a4 = 0.f, a5 = 0.f, a6 = 0.f, a7 = 0.f;

        if (t > 0) {
            if (warp == 0) {
                // Acquire probes, single poller (R6/R14-proven champion)
                while (ld_acquire_gpu(cnt + (size_t)(t - 1) * CNT_STRIDE) < wait_target) { }
                if (lane == 0) st_release_shared(&s_flag, t);
            } else {
                while (ld_acquire_shared(&s_flag) < t) { }
            }

            // This warp's 2KB h-chunk: 4 float4 per lane, all in flight at once
            const float4* hp4 = (const float4*)(Hout + (size_t)(t - 1) * H_DIM) + kq;
            float4 hb0 = __ldcg(hp4 + lane);
            float4 hb1 = __ldcg(hp4 + lane + 32);
            float4 hb2 = __ldcg(hp4 + lane + 64);
            float4 hb3 = __ldcg(hp4 + lane + 96);

#pragma unroll
            for (int i = 0; i < 4; i++) {
                const float4 hv = (i == 0) ? hb0 : (i == 1) ? hb1
                                : (i == 2) ? hb2 : hb3;
                const int idx = lane + 32 * i;
                float4 x;
                x = wr[0][idx]; a0 += x.x*hv.x + x.y*hv.y + x.z*hv.z + x.w*hv.w;
                x = wr[1][idx]; a1 += x.x*hv.x + x.y*hv.y + x.z*hv.z + x.w*hv.w;
                x = wr[2][idx]; a2 += x.x*hv.x + x.y*hv.y + x.z*hv.z + x.w*hv.w;
                x = wr[3][idx]; a3 += x.x*hv.x + x.y*hv.y + x.z*hv.z + x.w*hv.w;
                x = wr[4][idx]; a4 += x.x*hv.x + x.y*hv.y + x.z*hv.z + x.w*hv.w;
                x = wr[5][idx]; a5 += x.x*hv.x + x.y*hv.y + x.z*hv.z + x.w*hv.w;
                x = wr[6][idx]; a6 += x.x*hv.x + x.y*hv.y + x.z*hv.z + x.w*hv.w;
                x = wr[7][idx]; a7 += x.x*hv.x + x.y*hv.y + x.z*hv.z + x.w*hv.w;
            }
#pragma unroll
            for (int off = 16; off > 0; off >>= 1) {
                a0 += __shfl_xor_sync(0xffffffffu, a0, off);
                a1 += __shfl_xor_sync(0xffffffffu, a1, off);
                a2 += __shfl_xor_sync(0xffffffffu, a2, off);
                a3 += __shfl_xor_sync(0xffffffffu, a3, off);
                a4 += __shfl_xor_sync(0xffffffffu, a4, off);
                a5 += __shfl_xor_sync(0xffffffffu, a5, off);
                a6 += __shfl_xor_sync(0xffffffffu, a6, off);
                a7 += __shfl_xor_sync(0xffffffffu, a7, off);
            }
        }

        // lanes 0-7 park this warp's 8 row-partials in SMEM
        if (lane < 8) {
            const float v = (lane == 0) ? a0 : (lane == 1) ? a1
                          : (lane == 2) ? a2 : (lane == 3) ? a3
                          : (lane == 4) ? a4 : (lane == 5) ? a5
                          : (lane == 6) ? a6 : a7;
            s_part[ksl * ROWS_PER_CTA + r0 + lane] = v;
        }
        __syncthreads();   // all partials visible

        // SPLIT COMMIT: warps 0 and 4 each finalize their own row-group.
        if (ksl == 0) {
            if (lane < 8) {
                const int r = r0 + lane;
                const float s = s_part[r]
                              + s_part[ROWS_PER_CTA + r]
                              + s_part[2 * ROWS_PER_CTA + r]
                              + s_part[3 * ROWS_PER_CTA + r];
                __stcg(Hout + (size_t)t * H_DIM + row0 + r, tanhf(uval + s));
                fence_gpu();                    // R2-proven: fence by the storer
            }
            __syncwarp();
            if (lane == 0) red_release_gpu(cnt + (size_t)t * CNT_STRIDE);
        }
    }
}

// ---------------------------------------------------------------------------
extern "C" void kernel_launch(void* const* d_in, const int* in_sizes, int n_in,
                              void* d_out, int out_size)
{
    const float* input = (const float*)d_in[0];   // (1, S, I)
    const float* Wi0   = (const float*)d_in[1];   // (H, I)
    const float* bi0   = (const float*)d_in[2];   // (H)
    const float* WiR   = (const float*)d_in[3];   // (L-1, H, H)
    const float* biR   = (const float*)d_in[4];   // (L-1, H)
    const float* Wh    = (const float*)d_in[5];   // (L, H, H)
    const float* bh    = (const float*)d_in[6];   // (L, H)
    float* out = (float*)d_out;                   // (S, 1, H) contiguous

    float *U, *HA; int* cnt;
    cudaGetSymbolAddress((void**)&U,  g_U);
    cudaGetSymbolAddress((void**)&HA, g_HA);
    cudaGetSymbolAddress((void**)&cnt, g_cnt);

    cudaFuncSetAttribute(scan_kernel,
                         cudaFuncAttributeMaxDynamicSharedMemorySize,
                         SCAN_SMEM_BYTES);

    // Counters must be zero at the start of every replay (graph-captured node)
    cudaMemsetAsync(cnt, 0, S_LEN * CNT_STRIDE * sizeof(int));

    dim3 gemm_grid(H_DIM / 128, S_LEN / 128);   // (16, 8)

    // Layer 0: U = X @ Wi0^T + bi0 + bh[0]; then scan with Wh[0]
    gemm_bias_kernel<<<gemm_grid, 256>>>(input, Wi0, U, bi0, bh, S_LEN, H_DIM, I_DIM);
    scan_kernel<<<SCAN_CTAS, SCAN_THREADS, SCAN_SMEM_BYTES>>>(Wh, U, HA, cnt,
                                                              ARRIVALS_PER_STEP);

    // Layers 1..3
    for (int l = 1; l < L_NUM; l++) {
        const float* Wi_l = WiR + (size_t)(l - 1) * H_DIM * H_DIM;
        const float* bi_l = biR + (size_t)(l - 1) * H_DIM;
        const float* Wh_l = Wh  + (size_t)l * H_DIM * H_DIM;
        const float* bh_l = bh  + (size_t)l * H_DIM;
        float* dst = (l == L_NUM - 1) ? out : HA;

        gemm_bias_kernel<<<gemm_grid, 256>>>(HA, Wi_l, U, bi_l, bh_l,
                                             S_LEN, H_DIM, H_DIM);
        scan_kernel<<<SCAN_CTAS, SCAN_THREADS, SCAN_SMEM_BYTES>>>(Wh_l, U, dst, cnt,
                                                                  ARRIVALS_PER_STEP * (l + 1));
    }
}